// round 15
// baseline (speedup 1.0000x reference)
#include <cuda_runtime.h>
#include <cuda_fp16.h>
#include <math.h>
#include <stdint.h>

// ---------------------------------------------------------------------------
// CrossModalAttention on sm_103 — fp16 mma.sync (m16n8k16, fp32 accum),
// ldmatrix fragment loads everywhere:
//   cvt           : inputs + weights fp32 -> fp16 (one batched launch)
//   qkv proj      : ONE launch (grid.z=3), fp16 HMMA, bias, fp16 out
//   VT transpose  : per-head V^T fp16
//   scores_exp    : E = h2exp2((QK^T)*temp*log2e) fp16; SMEM-staged coalesced
//                   v4 stores; row partials PS. __launch_bounds__(256,3).
//   ctx_fused     : invl from PS (folded). GEMM directly on E; P = E*invl by
//                   LDS+stream pass; ctx scaled by invl in epilogue.
//   out proj      : fp16 HMMA + bias -> fp32
//   residual + LayerNorm (fp32)
// Shapes fixed: B=2, S=2048, HIDDEN=1024, HEADS=16, HDIM=64.
// ---------------------------------------------------------------------------

#define HIDDEN_ 1024
#define HEADS_  16
#define HDIM_   64
#define BATCH_  2
#define SEQ_    2048
#define MTOT_   (BATCH_*SEQ_)            // 4096
#define NROWS_  (BATCH_*HEADS_*SEQ_)     // 65536

static const long long LN_N  = (long long)MTOT_ * HIDDEN_;               // 4,194,304
static const long long ATT_N = (long long)BATCH_ * HEADS_ * SEQ_ * SEQ_; // 134,217,728

// Scratch (__device__ globals; 16B-aligned for vector ld/st)
__device__ __align__(16) __half g_q16in[(size_t)MTOT_ * HIDDEN_];
__device__ __align__(16) __half g_k16in[(size_t)MTOT_ * HIDDEN_];
__device__ __align__(16) __half g_v16in[(size_t)MTOT_ * HIDDEN_];
__device__ __align__(16) __half g_W16 [(size_t)4 * HIDDEN_ * HIDDEN_];   // Wq,Wk,Wv,Wo
__device__ __align__(16) __half g_Q16 [(size_t)MTOT_ * HIDDEN_];
__device__ __align__(16) __half g_K16 [(size_t)MTOT_ * HIDDEN_];
__device__ __align__(16) __half g_V16 [(size_t)MTOT_ * HIDDEN_];
__device__ __align__(16) __half g_VT16[(size_t)BATCH_ * HEADS_ * HDIM_ * SEQ_];
__device__ __align__(16) __half g_ctx16[(size_t)MTOT_ * HIDDEN_];
__device__ __align__(16) __half g_E  [(size_t)BATCH_ * HEADS_ * SEQ_ * SEQ_];
__device__ float  g_o  [(size_t)MTOT_ * HIDDEN_];
__device__ float  g_PS [(size_t)NROWS_ * 16];
__device__ float  g_Pfb[(size_t)BATCH_ * HEADS_ * SEQ_ * SEQ_];

// ---------------------------------------------------------------------------
// PTX helpers (sm_75+/sm_80+ portable)
// ---------------------------------------------------------------------------
__device__ __forceinline__ uint32_t smem_u32(const void* p) {
    return (uint32_t)__cvta_generic_to_shared(p);
}
__device__ __forceinline__ void cp_async16(uint32_t dst, const void* src) {
    asm volatile("cp.async.cg.shared.global [%0], [%1], 16;" :: "r"(dst), "l"(src));
}
__device__ __forceinline__ void cp_commit() { asm volatile("cp.async.commit_group;" ::: "memory"); }
template <int N>
__device__ __forceinline__ void cp_wait_group() {
    asm volatile("cp.async.wait_group %0;" :: "n"(N) : "memory");
}
__device__ __forceinline__ void st_cs_v4f(float* p, float4 v) {
    asm volatile("st.global.cs.v4.f32 [%0], {%1,%2,%3,%4};"
                 :: "l"(p), "f"(v.x), "f"(v.y), "f"(v.z), "f"(v.w) : "memory");
}
__device__ __forceinline__ void st_cs_v4h(__half* p, uint4 v) {
    asm volatile("st.global.cs.v4.u32 [%0], {%1,%2,%3,%4};"
                 :: "l"(p), "r"(v.x), "r"(v.y), "r"(v.z), "r"(v.w) : "memory");
}
// ldmatrix x4: 4x (8x8 b16) tiles -> 4 regs, lane groups supply addresses
__device__ __forceinline__ void ldsm_x4(uint32_t& r0, uint32_t& r1,
                                        uint32_t& r2, uint32_t& r3, uint32_t a) {
    asm volatile("ldmatrix.sync.aligned.m8n8.x4.shared.b16 {%0,%1,%2,%3}, [%4];"
                 : "=r"(r0), "=r"(r1), "=r"(r2), "=r"(r3) : "r"(a));
}
// D += A*B, m16n8k16 fp16 inputs, fp32 accumulate
__device__ __forceinline__ void mma16816(float* d, const uint32_t* a, const uint32_t* b) {
    asm volatile(
        "mma.sync.aligned.m16n8k16.row.col.f32.f16.f16.f32 "
        "{%0,%1,%2,%3}, {%4,%5,%6,%7}, {%8,%9}, {%0,%1,%2,%3};"
        : "+f"(d[0]), "+f"(d[1]), "+f"(d[2]), "+f"(d[3])
        : "r"(a[0]), "r"(a[1]), "r"(a[2]), "r"(a[3]), "r"(b[0]), "r"(b[1]));
}

// ---------------------------------------------------------------------------
// Batched fp32 -> fp16 conversion (7 tensors, grid.y selects)
// ---------------------------------------------------------------------------
struct Cvt7 {
    const float* src[7];
    __half*      dst[7];
    int          n8[7];
};
__global__ void __launch_bounds__(256)
cvt_kernel(Cvt7 c)
{
    const int z = blockIdx.y;
    const int i = blockIdx.x * 256 + threadIdx.x;
    if (i < c.n8[z]) {
        const float4* s = (const float4*)c.src[z] + (size_t)i * 2;
        float4 a = s[0], b = s[1];
        __half2 h0 = __floats2half2_rn(a.x, a.y);
        __half2 h1 = __floats2half2_rn(a.z, a.w);
        __half2 h2 = __floats2half2_rn(b.x, b.y);
        __half2 h3 = __floats2half2_rn(b.z, b.w);
        uint4 o;
        o.x = *(uint32_t*)&h0; o.y = *(uint32_t*)&h1;
        o.z = *(uint32_t*)&h2; o.w = *(uint32_t*)&h3;
        ((uint4*)c.dst[z])[i] = o;
    }
}

// ---------------------------------------------------------------------------
// fp16 GEMM body: C[m,n] = sum_k A[m,k]*B[n,k] + bias[n]
// BM=BN=128, BK=64 halves. 256 threads = 8 warps (2x4). LDH=72.
// Fragment loads via ldmatrix.x4 (A: per-i; B: paired jj).
// ---------------------------------------------------------------------------
template <bool OUT16>
__device__ __forceinline__ void gemm16_body(
    const __half* __restrict__ A, const __half* __restrict__ Bm,
    const float* __restrict__ bias, void* __restrict__ Cv,
    int K, int lda, int ldb, int ldc, int bx, int by)
{
    constexpr int LDH = 72;
    constexpr int STAGE = 128 * LDH;

    extern __shared__ __half smh[];
    __half* As = smh;
    __half* Bs = smh + 2 * STAGE;

    const int tid  = threadIdx.x;
    const int warp = tid >> 5;
    const int lane = tid & 31;
    const int wr = warp & 1, wc = warp >> 1;
    const int g = lane >> 2, t = lane & 3;
    const int row0 = by * 128;
    const int col0 = bx * 128;

    // ldmatrix per-lane address components
    const int lane8   = lane & 7;
    const int laneh8  = ((lane >> 3) & 1) * 8;
    const int lane16_8 = (lane >> 4) * 8;
    const uint32_t aOff = (uint32_t)(((wr * 64 + laneh8 + lane8) * LDH + lane16_8) * 2);
    const uint32_t bOff = (uint32_t)(((wc * 32 + lane16_8 + lane8) * LDH + laneh8) * 2);
    const uint32_t smA = smem_u32(As), smB = smem_u32(Bs);

    float acc[4][4][4];
#pragma unroll
    for (int i = 0; i < 4; ++i)
#pragma unroll
        for (int j = 0; j < 4; ++j)
#pragma unroll
            for (int q = 0; q < 4; ++q) acc[i][j][q] = 0.0f;

    auto load_tile = [&](int kt) {
        const int st = kt & 1;
        const __half* Ag = A + (size_t)row0 * lda + kt * 64;
        __half* Ad = As + st * STAGE;
#pragma unroll
        for (int i = 0; i < 4; ++i) {
            int id = tid + i * 256;
            int r = id >> 3, c = id & 7;
            cp_async16(smem_u32(Ad + r * LDH + c * 8), Ag + (size_t)r * lda + c * 8);
        }
        const __half* Bg = Bm + (size_t)col0 * ldb + kt * 64;
        __half* Bd = Bs + st * STAGE;
#pragma unroll
        for (int i = 0; i < 4; ++i) {
            int id = tid + i * 256;
            int r = id >> 3, c = id & 7;
            cp_async16(smem_u32(Bd + r * LDH + c * 8), Bg + (size_t)r * ldb + c * 8);
        }
        cp_commit();
    };

    const int T = K >> 6;
    load_tile(0);
    for (int kt = 0; kt < T; ++kt) {
        if (kt + 1 < T) { load_tile(kt + 1); cp_wait_group<1>(); }
        else            { cp_wait_group<0>(); }
        __syncthreads();

        const uint32_t aT = smA + (uint32_t)((kt & 1) * STAGE * 2) + aOff;
        const uint32_t bT = smB + (uint32_t)((kt & 1) * STAGE * 2) + bOff;
#pragma unroll
        for (int s = 0; s < 4; ++s) {
            uint32_t a[4][4], b[4][2];
#pragma unroll
            for (int i = 0; i < 4; ++i)
                ldsm_x4(a[i][0], a[i][1], a[i][2], a[i][3],
                        aT + (uint32_t)(i * 16 * LDH * 2 + s * 32));
#pragma unroll
            for (int jj = 0; jj < 2; ++jj)
                ldsm_x4(b[2 * jj][0], b[2 * jj][1], b[2 * jj + 1][0], b[2 * jj + 1][1],
                        bT + (uint32_t)(jj * 16 * LDH * 2 + s * 32));
#pragma unroll
            for (int i = 0; i < 4; ++i)
#pragma unroll
                for (int j = 0; j < 4; ++j)
                    mma16816(acc[i][j], a[i], b[j]);
        }
        __syncthreads();
    }

#pragma unroll
    for (int i = 0; i < 4; ++i) {
#pragma unroll
        for (int j = 0; j < 4; ++j) {
            const int r = row0 + wr * 64 + i * 16 + g;
            const int c = col0 + wc * 32 + j * 8 + 2 * t;
            const float bx_ = bias[c], by_ = bias[c + 1];
            float v00 = acc[i][j][0] + bx_, v01 = acc[i][j][1] + by_;
            float v10 = acc[i][j][2] + bx_, v11 = acc[i][j][3] + by_;
            if (OUT16) {
                __half* C16 = (__half*)Cv;
                __half2 h0 = __floats2half2_rn(v00, v01);
                __half2 h1 = __floats2half2_rn(v10, v11);
                *(__half2*)(C16 + (size_t)r * ldc + c)       = h0;
                *(__half2*)(C16 + (size_t)(r + 8) * ldc + c) = h1;
            } else {
                float* C32 = (float*)Cv;
                *(float2*)(C32 + (size_t)r * ldc + c)       = make_float2(v00, v01);
                *(float2*)(C32 + (size_t)(r + 8) * ldc + c) = make_float2(v10, v11);
            }
        }
    }
}

struct QKV16 {
    const __half* A[3];
    const __half* W[3];
    const float*  bias[3];
    __half*       C[3];
};
__global__ void __launch_bounds__(256)
gemm16_qkv(QKV16 p)
{
    const int z = blockIdx.z;
    gemm16_body<true>(p.A[z], p.W[z], p.bias[z], p.C[z],
                      HIDDEN_, HIDDEN_, HIDDEN_, HIDDEN_, blockIdx.x, blockIdx.y);
}
__global__ void __launch_bounds__(256)
gemm16_o(const __half* __restrict__ A, const __half* __restrict__ Bm,
         const float* __restrict__ bias, float* __restrict__ C)
{
    gemm16_body<false>(A, Bm, bias, C, HIDDEN_, HIDDEN_, HIDDEN_, HIDDEN_,
                       blockIdx.x, blockIdx.y);
}

// ---------------------------------------------------------------------------
// Per-head V transpose (fp16): VT[bh][d][k] = V[b*SEQ+k][h*HDIM+d]
// ---------------------------------------------------------------------------
__global__ void __launch_bounds__(256)
transpose_v_kernel(const __half* __restrict__ V, __half* __restrict__ VT)
{
    __shared__ __half t[32][34];
    const int bh = blockIdx.z;
    const int b = bh / HEADS_, h = bh % HEADS_;
    const int k0 = blockIdx.x * 32;
    const int d0 = blockIdx.y * 32;
    const int tx = threadIdx.x & 31;
    const int ty = threadIdx.x >> 5;
    const __half* src = V + (size_t)(b * SEQ_) * HIDDEN_ + h * HDIM_;
#pragma unroll
    for (int j = 0; j < 4; ++j)
        t[ty + 8 * j][tx] = src[(size_t)(k0 + ty + 8 * j) * HIDDEN_ + d0 + tx];
    __syncthreads();
    __half* dst = VT + (size_t)bh * HDIM_ * SEQ_;
#pragma unroll
    for (int j = 0; j < 4; ++j)
        dst[(size_t)(d0 + ty + 8 * j) * SEQ_ + k0 + tx] = t[tx][ty + 8 * j];
}

// ---------------------------------------------------------------------------
// Scores + exp (fp16 mma, ldmatrix): per CTA = 128x128 S tile, d=64.
// E = h2exp2(S*temp*log2e) fp16, staged in SMEM (stride 136, conflict-free)
// then coalesced v4 stores. Row partials -> PS. (256,3).
// ---------------------------------------------------------------------------
__global__ void __launch_bounds__(256, 3)
scores_exp_kernel(const __half* __restrict__ Q, const __half* __restrict__ K,
                  __half* __restrict__ E, float* __restrict__ PS,
                  const float* __restrict__ tptr)
{
    constexpr int LDH = 72;
    constexpr int LDE = 136;
    extern __shared__ __half smh[];
    __half* Qs = smh;                  // 128*72
    __half* Ks = smh + 128 * LDH;      // 128*72
    __half* Es = smh;                  // reuse after mma: 128*136 <= 2*128*72
    __shared__ float red[512];

    const int bx = blockIdx.x;
    const int by = blockIdx.y;
    const int bh = blockIdx.z;
    const int b = bh >> 4, h = bh & 15;
    const int tid = threadIdx.x, lane = tid & 31, warp = tid >> 5;
    const int wr = warp & 1, wc = warp >> 1;
    const int g = lane >> 2, t = lane & 3;
    const float tl2e = (*tptr) * 1.4426950408889634f;

    const int lane8   = lane & 7;
    const int laneh8  = ((lane >> 3) & 1) * 8;
    const int lane16_8 = (lane >> 4) * 8;
    const uint32_t aAddr = smem_u32(Qs)
        + (uint32_t)(((wr * 64 + laneh8 + lane8) * LDH + lane16_8) * 2);
    const uint32_t bAddr = smem_u32(Ks)
        + (uint32_t)(((wc * 32 + lane16_8 + lane8) * LDH + laneh8) * 2);

    const __half* Qg = Q + ((size_t)(b * SEQ_) + by * 128) * HIDDEN_ + h * HDIM_;
    const __half* Kg = K + ((size_t)(b * SEQ_) + bx * 128) * HIDDEN_ + h * HDIM_;
    __half* Eg = E + ((size_t)bh * SEQ_ + by * 128) * SEQ_ + bx * 128;

#pragma unroll
    for (int i = 0; i < 4; ++i) {
        int id = tid + i * 256;
        int r = id >> 3, c = id & 7;
        cp_async16(smem_u32(Qs + r * LDH + c * 8), Qg + (size_t)r * HIDDEN_ + c * 8);
    }
#pragma unroll
    for (int i = 0; i < 4; ++i) {
        int id = tid + i * 256;
        int r = id >> 3, c = id & 7;
        cp_async16(smem_u32(Ks + r * LDH + c * 8), Kg + (size_t)r * HIDDEN_ + c * 8);
    }
    cp_commit();
    cp_wait_group<0>();
    __syncthreads();

    float acc[4][4][4];
#pragma unroll
    for (int i = 0; i < 4; ++i)
#pragma unroll
        for (int j = 0; j < 4; ++j)
#pragma unroll
            for (int q = 0; q < 4; ++q) acc[i][j][q] = 0.0f;

#pragma unroll
    for (int s = 0; s < 4; ++s) {
        uint32_t a[4][4], bf[4][2];
#pragma unroll
        for (int i = 0; i < 4; ++i)
            ldsm_x4(a[i][0], a[i][1], a[i][2], a[i][3],
                    aAddr + (uint32_t)(i * 16 * LDH * 2 + s * 32));
#pragma unroll
        for (int jj = 0; jj < 2; ++jj)
            ldsm_x4(bf[2 * jj][0], bf[2 * jj][1], bf[2 * jj + 1][0], bf[2 * jj + 1][1],
                    bAddr + (uint32_t)(jj * 16 * LDH * 2 + s * 32));
#pragma unroll
        for (int i = 0; i < 4; ++i)
#pragma unroll
            for (int j = 0; j < 4; ++j)
                mma16816(acc[i][j], a[i], bf[j]);
    }
    __syncthreads();                   // Qs/Ks reads complete -> reuse as Es

    // E = 2^(s*temp*log2e) via h2exp2; stage in Es; sums from fp16 values
    float rs0[4], rs1[4];
#pragma unroll
    for (int i = 0; i < 4; ++i) { rs0[i] = 0.f; rs1[i] = 0.f; }
#pragma unroll
    for (int i = 0; i < 4; ++i) {
        const int rA = wr * 64 + i * 16 + g;
#pragma unroll
        for (int j = 0; j < 4; ++j) {
            const int c = wc * 32 + j * 8 + 2 * t;
            __half2 e01 = h2exp2(__floats2half2_rn(acc[i][j][0] * tl2e, acc[i][j][1] * tl2e));
            __half2 e23 = h2exp2(__floats2half2_rn(acc[i][j][2] * tl2e, acc[i][j][3] * tl2e));
            *(__half2*)(Es + rA * LDE + c)       = e01;
            *(__half2*)(Es + (rA + 8) * LDE + c) = e23;
            float2 f0 = __half22float2(e01);
            float2 f1 = __half22float2(e23);
            rs0[i] += f0.x + f0.y;
            rs1[i] += f1.x + f1.y;
        }
    }
    __syncthreads();

    // coalesced v4 stores: 128 rows x 128 halves
#pragma unroll
    for (int p = 0; p < 8; ++p) {
        int id = tid + p * 256;
        int r = id >> 4, cc = id & 15;
        uint4 v = *(const uint4*)(Es + r * LDE + cc * 8);
        st_cs_v4h(Eg + (size_t)r * SEQ_ + cc * 8, v);
    }

    // row-sum reduction
#pragma unroll
    for (int i = 0; i < 4; ++i) {
        rs0[i] += __shfl_xor_sync(0xffffffffu, rs0[i], 1);
        rs0[i] += __shfl_xor_sync(0xffffffffu, rs0[i], 2);
        rs1[i] += __shfl_xor_sync(0xffffffffu, rs1[i], 1);
        rs1[i] += __shfl_xor_sync(0xffffffffu, rs1[i], 2);
    }
    if (t == 0) {
#pragma unroll
        for (int i = 0; i < 4; ++i) {
            red[wc * 128 + wr * 64 + i * 16 + g]     = rs0[i];
            red[wc * 128 + wr * 64 + i * 16 + g + 8] = rs1[i];
        }
    }
    __syncthreads();
    if (tid < 128) {
        float s = red[tid] + red[128 + tid] + red[256 + tid] + red[384 + tid];
        PS[((size_t)bh * SEQ_ + by * 128 + tid) * 16 + bx] = s;
    }
}

// ---------------------------------------------------------------------------
// Context fused (fp16 mma, ldmatrix): per CTA = (bh, 128-row strip), BK=64.
// P@V == diag(invl)*(E@V): mma consumes E from cp.async SMEM tiles; P=E*invl
// emitted by LDS+normalize+stream pass; ctx scaled by invl in epilogue.
// ---------------------------------------------------------------------------
__global__ void __launch_bounds__(256)
ctx_fused_kernel(const __half* __restrict__ E, const float* __restrict__ PS,
                 const __half* __restrict__ VT, float* __restrict__ P,
                 __half* __restrict__ CTX)
{
    constexpr int LDH = 72;
    constexpr int AS_STAGE = 128 * LDH;    // halves
    constexpr int BS_STAGE = 64 * LDH;
    extern __shared__ __half smh[];
    __half* As = smh;                      // 2 stages (E tiles)
    __half* Bs = smh + 2 * AS_STAGE;       // 2 stages (VT tiles)
    __shared__ float s_inv[128];

    const int strip = blockIdx.x;
    const int bh = blockIdx.y;
    const int b = bh >> 4, h = bh & 15;
    const int tid = threadIdx.x, lane = tid & 31, warp = tid >> 5;
    const int wr = warp & 1, wc = warp >> 1;
    const int g = lane >> 2, t = lane & 3;

    const int lane8   = lane & 7;
    const int laneh8  = ((lane >> 3) & 1) * 8;
    const int lane16_8 = (lane >> 4) * 8;
    const uint32_t aOff = (uint32_t)(((wr * 64 + laneh8 + lane8) * LDH + lane16_8) * 2);
    const uint32_t bOff = (uint32_t)(((wc * 16 + lane16_8 + lane8) * LDH + laneh8) * 2);
    const uint32_t smA = smem_u32(As), smB = smem_u32(Bs);

    const __half* Eg = E + ((size_t)bh * SEQ_ + strip * 128) * SEQ_;
    float*        Pg = P + ((size_t)bh * SEQ_ + strip * 128) * SEQ_;
    const __half* Vg = VT + (size_t)bh * HDIM_ * SEQ_;
    __half*       Cg = CTX + ((size_t)(b * SEQ_) + strip * 128) * HIDDEN_ + h * HDIM_;

    // invl folded in: each of 128 threads sums its row's 16 partials
    if (tid < 128) {
        const float4* ps = (const float4*)(PS + ((size_t)bh * SEQ_ + strip * 128 + tid) * 16);
        float4 a = ps[0], b2 = ps[1], c2 = ps[2], d2 = ps[3];
        float s = (a.x + a.y + a.z + a.w) + (b2.x + b2.y + b2.z + b2.w)
                + (c2.x + c2.y + c2.z + c2.w) + (d2.x + d2.y + d2.z + d2.w);
        s_inv[tid] = 1.0f / s;
    }

    auto load_tile = [&](int kt) {
        __half* Ad = As + (kt & 1) * AS_STAGE;
#pragma unroll
        for (int i = 0; i < 4; ++i) {
            int id = tid + i * 256;
            int r = id >> 3, c8 = id & 7;
            cp_async16(smem_u32(Ad + r * LDH + c8 * 8), Eg + (size_t)r * SEQ_ + kt * 64 + c8 * 8);
        }
        __half* Bd = Bs + (kt & 1) * BS_STAGE;
#pragma unroll
        for (int i = 0; i < 2; ++i) {
            int id = tid + i * 256;
            int r = id >> 3, c8 = id & 7;
            cp_async16(smem_u32(Bd + r * LDH + c8 * 8), Vg + (size_t)r * SEQ_ + kt * 64 + c8 * 8);
        }
        cp_commit();
    };

    float ctx[4][2][4];
#pragma unroll
    for (int i = 0; i < 4; ++i)
#pragma unroll
        for (int j = 0; j < 2; ++j)
#pragma unroll
            for (int q = 0; q < 4; ++q) ctx[i][j][q] = 0.f;

    load_tile(0);
    for (int kt = 0; kt < 32; ++kt) {
        if (kt + 1 < 32) { load_tile(kt + 1); cp_wait_group<1>(); }
        else             { cp_wait_group<0>(); }
        __syncthreads();               // tile kt ready; s_inv visible (kt=0)

        // P = E*invl streaming pass from the SMEM tile
        const __half* Ad = As + (kt & 1) * AS_STAGE;
#pragma unroll
        for (int i = 0; i < 4; ++i) {
            int id = tid + i * 256;
            int r = id >> 3, c8 = id & 7;
            const float inv = s_inv[r];
            uint4 v = *(const uint4*)(Ad + r * LDH + c8 * 8);
            float2 f0 = __half22float2(*(__half2*)&v.x);
            float2 f1 = __half22float2(*(__half2*)&v.y);
            float2 f2 = __half22float2(*(__half2*)&v.z);
            float2 f3 = __half22float2(*(__half2*)&v.w);
            float* pd = Pg + (size_t)r * SEQ_ + kt * 64 + c8 * 8;
            st_cs_v4f(pd,     make_float4(f0.x * inv, f0.y * inv, f1.x * inv, f1.y * inv));
            st_cs_v4f(pd + 4, make_float4(f2.x * inv, f2.y * inv, f3.x * inv, f3.y * inv));
        }

        // ctx_raw += E(128q x 64k) @ VT(64d x 64k)^T  (unnormalized)
        const uint32_t aT = smA + (uint32_t)((kt & 1) * AS_STAGE * 2) + aOff;
        const uint32_t bT = smB + (uint32_t)((kt & 1) * BS_STAGE * 2) + bOff;
#pragma unroll
        for (int s = 0; s < 4; ++s) {        // 64 keys = 4 x k16
            uint32_t a[4][4], bf[2][2];
#pragma unroll
            for (int i = 0; i < 4; ++i)
                ldsm_x4(a[i][0], a[i][1], a[i][2], a[i][3],
                        aT + (uint32_t)(i * 16 * LDH * 2 + s * 32));
            ldsm_x4(bf[0][0], bf[0][1], bf[1][0], bf[1][1],
                    bT + (uint32_t)(s * 32));
#pragma unroll
            for (int i = 0; i < 4; ++i)
#pragma unroll
                for (int j = 0; j < 2; ++j)
                    mma16816(ctx[i][j], a[i], bf[j]);
        }
        __syncthreads();               // reads of As/Bs[kt&1] done before reuse
    }

    // epilogue: ctx = diag(invl) * ctx_raw, store fp16
    float linv[4][2];
#pragma unroll
    for (int i = 0; i < 4; ++i) {
        linv[i][0] = s_inv[wr * 64 + i * 16 + g];
        linv[i][1] = s_inv[wr * 64 + i * 16 + g + 8];
    }
#pragma unroll
    for (int i = 0; i < 4; ++i) {
        const int rA = wr * 64 + i * 16 + g;
#pragma unroll
        for (int j = 0; j < 2; ++j) {
            const int c = wc * 16 + j * 8 + 2 * t;
            __half2 h0 = __floats2half2_rn(ctx[i][j][0] * linv[i][0], ctx[i][j][1] * linv[i][0]);
            __half2 h1 = __floats2half2_rn(ctx[i][j][2] * linv[i][1], ctx[i][j][3] * linv[i][1]);
            *(__half2*)(Cg + (size_t)rA * HIDDEN_ + c)       = h0;
            *(__half2*)(Cg + (size_t)(rA + 8) * HIDDEN_ + c) = h1;
        }
    }
}

// ---------------------------------------------------------------------------
// Residual + LayerNorm (fp32)
// ---------------------------------------------------------------------------
__global__ void __launch_bounds__(256)
ln_kernel(const float* __restrict__ o, const float* __restrict__ resid,
          const float* __restrict__ gamma, const float* __restrict__ beta,
          float* __restrict__ out)
{
    __shared__ float red1[8], red2[8];
    __shared__ float bmean, binv;

    const size_t row = blockIdx.x;
    const int tid = threadIdx.x;
    const int lane = tid & 31, wid = tid >> 5;
    const float* po = o + row * HIDDEN_;
    const float* pr = resid + row * HIDDEN_;

    float x[4];
    float s = 0.0f, s2 = 0.0f;
#pragma unroll
    for (int u = 0; u < 4; ++u) {
        const int idx = tid + 256 * u;
        x[u] = po[idx] + pr[idx];
        s += x[u];
        s2 += x[u] * x[u];
    }
#pragma unroll
    for (int of = 16; of; of >>= 1) {
        s  += __shfl_xor_sync(0xffffffffu, s,  of);
        s2 += __shfl_xor_sync(0xffffffffu, s2, of);
    }
    if (lane == 0) { red1[wid] = s; red2[wid] = s2; }
    __syncthreads();
    if (wid == 0) {
        float t1 = (lane < 8) ? red1[lane] : 0.0f;
        float t2 = (lane < 8) ? red2[lane] : 0.0f;
#pragma unroll
        for (int of = 16; of; of >>= 1) {
            t1 += __shfl_xor_sync(0xffffffffu, t1, of);
            t2 += __shfl_xor_sync(0xffffffffu, t2, of);
        }
        if (lane == 0) {
            const float mean = t1 * (1.0f / HIDDEN_);
            const float var  = t2 * (1.0f / HIDDEN_) - mean * mean;
            bmean = mean;
            binv  = rsqrtf(var + 1e-5f);
        }
    }
    __syncthreads();
    const float mean = bmean, inv = binv;
#pragma unroll
    for (int u = 0; u < 4; ++u) {
        const int idx = tid + 256 * u;
        out[row * HIDDEN_ + idx] = (x[u] - mean) * inv * gamma[idx] + beta[idx];
    }
}

// ---------------------------------------------------------------------------
static const int DSM_GEMM16   = 4 * 128 * 72 * 2;                  // 73728
static const int DSM_SCORES16 = 2 * 128 * 72 * 2;                  // 36864
static const int DSM_CTX16    = (2 * 128 * 72 + 2 * 64 * 72) * 2;  // 55296

extern "C" void kernel_launch(void* const* d_in, const int* in_sizes, int n_in,
                              void* d_out, int out_size)
{
    const float* query = (const float*)d_in[0];
    const float* key_  = (const float*)d_in[1];
    const float* value = (const float*)d_in[2];
    const float* Wq = (const float*)d_in[3];
    const float* bq = (const float*)d_in[4];
    const float* Wk = (const float*)d_in[5];
    const float* bk = (const float*)d_in[6];
    const float* Wv = (const float*)d_in[7];
    const float* bv = (const float*)d_in[8];
    const float* Wo = (const float*)d_in[9];
    const float* bo = (const float*)d_in[10];
    const float* gamma = (const float*)d_in[11];
    const float* beta  = (const float*)d_in[12];
    const float* temp  = (const float*)d_in[13];

    cudaFuncSetAttribute(gemm16_qkv, cudaFuncAttributeMaxDynamicSharedMemorySize, DSM_GEMM16);
    cudaFuncSetAttribute(gemm16_o,   cudaFuncAttributeMaxDynamicSharedMemorySize, DSM_GEMM16);
    cudaFuncSetAttribute(scores_exp_kernel, cudaFuncAttributeMaxDynamicSharedMemorySize, DSM_SCORES16);
    cudaFuncSetAttribute(ctx_fused_kernel,  cudaFuncAttributeMaxDynamicSharedMemorySize, DSM_CTX16);

    float* out_ln = (float*)d_out;
    __half *pQin, *pKin, *pVin, *pW16, *pQ16, *pK16, *pV16, *pVT16, *pCtx16, *pE;
    float *pO, *pPS, *pP;
    cudaGetSymbolAddress((void**)&pQin,  g_q16in);
    cudaGetSymbolAddress((void**)&pKin,  g_k16in);
    cudaGetSymbolAddress((void**)&pVin,  g_v16in);
    cudaGetSymbolAddress((void**)&pW16,  g_W16);
    cudaGetSymbolAddress((void**)&pQ16,  g_Q16);
    cudaGetSymbolAddress((void**)&pK16,  g_K16);
    cudaGetSymbolAddress((void**)&pV16,  g_V16);
    cudaGetSymbolAddress((void**)&pVT16, g_VT16);
    cudaGetSymbolAddress((void**)&pCtx16,g_ctx16);
    cudaGetSymbolAddress((void**)&pE,    g_E);
    cudaGetSymbolAddress((void**)&pO,    g_o);
    cudaGetSymbolAddress((void**)&pPS,   g_PS);
    if ((long long)out_size >= LN_N + ATT_N) {
        pP = out_ln + LN_N;           // attn_weights are part of the output
    } else {
        cudaGetSymbolAddress((void**)&pP, g_Pfb);
    }
    const int WN = HIDDEN_ * HIDDEN_;

    // --- fp32 -> fp16 conversions (one batched launch)
    {
        Cvt7 c;
        c.src[0] = query; c.dst[0] = pQin;          c.n8[0] = (MTOT_ * HIDDEN_) / 8;
        c.src[1] = key_;  c.dst[1] = pKin;          c.n8[1] = (MTOT_ * HIDDEN_) / 8;
        c.src[2] = value; c.dst[2] = pVin;          c.n8[2] = (MTOT_ * HIDDEN_) / 8;
        c.src[3] = Wq;    c.dst[3] = pW16 + 0ll*WN; c.n8[3] = WN / 8;
        c.src[4] = Wk;    c.dst[4] = pW16 + 1ll*WN; c.n8[4] = WN / 8;
        c.src[5] = Wv;    c.dst[5] = pW16 + 2ll*WN; c.n8[5] = WN / 8;
        c.src[6] = Wo;    c.dst[6] = pW16 + 3ll*WN; c.n8[6] = WN / 8;
        dim3 g((MTOT_ * HIDDEN_ / 8 + 255) / 256, 7, 1);
        cvt_kernel<<<g, 256>>>(c);
    }

    // --- Merged Q/K/V projections (fp16)
    {
        QKV16 p;
        p.A[0] = pQin; p.A[1] = pKin; p.A[2] = pVin;
        p.W[0] = pW16; p.W[1] = pW16 + 1ll*WN; p.W[2] = pW16 + 2ll*WN;
        p.bias[0] = bq; p.bias[1] = bk; p.bias[2] = bv;
        p.C[0] = pQ16; p.C[1] = pK16; p.C[2] = pV16;
        dim3 g(HIDDEN_ / 128, MTOT_ / 128, 3);
        gemm16_qkv<<<g, 256, DSM_GEMM16>>>(p);
    }

    // --- VT transpose (fp16)
    {
        dim3 g(SEQ_ / 32, HDIM_ / 32, BATCH_ * HEADS_);
        transpose_v_kernel<<<g, 256>>>(pV16, pVT16);
    }

    // --- Scores + exp (h2exp2, coalesced fp16 E) + partial sums
    {
        dim3 g(SEQ_ / 128, SEQ_ / 128, BATCH_ * HEADS_);
        scores_exp_kernel<<<g, 256, DSM_SCORES16>>>(pQ16, pK16, pE, pPS, temp);
    }

    // --- Context fused: GEMM on E + P stream + invl epilogue
    {
        dim3 g(SEQ_ / 128, BATCH_ * HEADS_, 1);
        ctx_fused_kernel<<<g, 256, DSM_CTX16>>>(pE, pPS, pVT16, pP, pCtx16);
    }

    // --- Output projection: o = ctx @ Wo^T + bo (fp32 out)
    {
        dim3 g(HIDDEN_ / 128, MTOT_ / 128, 1);
        gemm16_o<<<g, 256, DSM_GEMM16>>>(pCtx16, pW16 + 3ll*WN, bo, pO);
    }

    // --- Residual + LayerNorm
    ln_kernel<<<(unsigned)MTOT_, 256>>>(pO, query, gamma, beta, out_ln);
}

// round 16
// speedup vs baseline: 1.4922x; 1.4922x over previous
#include <cuda_runtime.h>
#include <cuda_fp16.h>
#include <math.h>
#include <stdint.h>

// ---------------------------------------------------------------------------
// CrossModalAttention on sm_103 — fp16 mma.sync (m16n8k16, fp32 accum):
//   cvt           : inputs + weights fp32 -> fp16 (one batched launch)
//   qkv proj      : ONE launch (grid.z=3), fp16 HMMA, bias, fp16 out
//   VT transpose  : per-head V^T fp16
//   scores_exp    : E = h2exp2((QK^T)*temp*log2e) fp16; SMEM-staged coalesced
//                   v4 stores; row partials PS. __launch_bounds__(256,3).
//   ctx_fused     : invl from PS (folded); stream fp16 E (BK=64),
//                   P = E*invl -> fp32 gmem (attn out), fp16(P) -> SMEM,
//                   ctx += P @ VT^T. __launch_bounds__(256) (no reg cap).
//   out proj      : fp16 HMMA + bias -> fp32
//   residual + LayerNorm (fp32)
// Shapes fixed: B=2, S=2048, HIDDEN=1024, HEADS=16, HDIM=64.
// (R13 configuration — measured best at 456.0 us.)
// ---------------------------------------------------------------------------

#define HIDDEN_ 1024
#define HEADS_  16
#define HDIM_   64
#define BATCH_  2
#define SEQ_    2048
#define MTOT_   (BATCH_*SEQ_)            // 4096
#define NROWS_  (BATCH_*HEADS_*SEQ_)     // 65536

static const long long LN_N  = (long long)MTOT_ * HIDDEN_;               // 4,194,304
static const long long ATT_N = (long long)BATCH_ * HEADS_ * SEQ_ * SEQ_; // 134,217,728

// Scratch (__device__ globals; 16B-aligned for vector ld/st)
__device__ __align__(16) __half g_q16in[(size_t)MTOT_ * HIDDEN_];
__device__ __align__(16) __half g_k16in[(size_t)MTOT_ * HIDDEN_];
__device__ __align__(16) __half g_v16in[(size_t)MTOT_ * HIDDEN_];
__device__ __align__(16) __half g_W16 [(size_t)4 * HIDDEN_ * HIDDEN_];   // Wq,Wk,Wv,Wo
__device__ __align__(16) __half g_Q16 [(size_t)MTOT_ * HIDDEN_];
__device__ __align__(16) __half g_K16 [(size_t)MTOT_ * HIDDEN_];
__device__ __align__(16) __half g_V16 [(size_t)MTOT_ * HIDDEN_];
__device__ __align__(16) __half g_VT16[(size_t)BATCH_ * HEADS_ * HDIM_ * SEQ_];
__device__ __align__(16) __half g_ctx16[(size_t)MTOT_ * HIDDEN_];
__device__ __align__(16) __half g_E  [(size_t)BATCH_ * HEADS_ * SEQ_ * SEQ_];
__device__ float  g_o  [(size_t)MTOT_ * HIDDEN_];
__device__ float  g_PS [(size_t)NROWS_ * 16];
__device__ float  g_Pfb[(size_t)BATCH_ * HEADS_ * SEQ_ * SEQ_];

// ---------------------------------------------------------------------------
// PTX helpers (sm_80+ portable)
// ---------------------------------------------------------------------------
__device__ __forceinline__ uint32_t smem_u32(const void* p) {
    return (uint32_t)__cvta_generic_to_shared(p);
}
__device__ __forceinline__ void cp_async16(uint32_t dst, const void* src) {
    asm volatile("cp.async.cg.shared.global [%0], [%1], 16;" :: "r"(dst), "l"(src));
}
__device__ __forceinline__ void cp_commit() { asm volatile("cp.async.commit_group;" ::: "memory"); }
template <int N>
__device__ __forceinline__ void cp_wait_group() {
    asm volatile("cp.async.wait_group %0;" :: "n"(N) : "memory");
}
__device__ __forceinline__ void st_cs_v4f(float* p, float4 v) {
    asm volatile("st.global.cs.v4.f32 [%0], {%1,%2,%3,%4};"
                 :: "l"(p), "f"(v.x), "f"(v.y), "f"(v.z), "f"(v.w) : "memory");
}
__device__ __forceinline__ void st_cs_v4h(__half* p, uint4 v) {
    asm volatile("st.global.cs.v4.u32 [%0], {%1,%2,%3,%4};"
                 :: "l"(p), "r"(v.x), "r"(v.y), "r"(v.z), "r"(v.w) : "memory");
}
__device__ __forceinline__ uint4 ld_cs_v4u(const void* p) {
    uint4 v;
    asm volatile("ld.global.cs.v4.u32 {%0,%1,%2,%3}, [%4];"
                 : "=r"(v.x), "=r"(v.y), "=r"(v.z), "=r"(v.w) : "l"(p));
    return v;
}
// D += A*B, m16n8k16 fp16 inputs, fp32 accumulate
__device__ __forceinline__ void mma16816(float* d, const uint32_t* a, const uint32_t* b) {
    asm volatile(
        "mma.sync.aligned.m16n8k16.row.col.f32.f16.f16.f32 "
        "{%0,%1,%2,%3}, {%4,%5,%6,%7}, {%8,%9}, {%0,%1,%2,%3};"
        : "+f"(d[0]), "+f"(d[1]), "+f"(d[2]), "+f"(d[3])
        : "r"(a[0]), "r"(a[1]), "r"(a[2]), "r"(a[3]), "r"(b[0]), "r"(b[1]));
}

// ---------------------------------------------------------------------------
// Batched fp32 -> fp16 conversion (7 tensors, grid.y selects)
// ---------------------------------------------------------------------------
struct Cvt7 {
    const float* src[7];
    __half*      dst[7];
    int          n8[7];
};
__global__ void __launch_bounds__(256)
cvt_kernel(Cvt7 c)
{
    const int z = blockIdx.y;
    const int i = blockIdx.x * 256 + threadIdx.x;
    if (i < c.n8[z]) {
        const float4* s = (const float4*)c.src[z] + (size_t)i * 2;
        float4 a = s[0], b = s[1];
        __half2 h0 = __floats2half2_rn(a.x, a.y);
        __half2 h1 = __floats2half2_rn(a.z, a.w);
        __half2 h2 = __floats2half2_rn(b.x, b.y);
        __half2 h3 = __floats2half2_rn(b.z, b.w);
        uint4 o;
        o.x = *(uint32_t*)&h0; o.y = *(uint32_t*)&h1;
        o.z = *(uint32_t*)&h2; o.w = *(uint32_t*)&h3;
        ((uint4*)c.dst[z])[i] = o;
    }
}

// ---------------------------------------------------------------------------
// fp16 GEMM body: C[m,n] = sum_k A[m,k]*B[n,k] + bias[n]
// BM=BN=128, BK=64 halves. 256 threads = 8 warps (2x4). LDH=72.
// ---------------------------------------------------------------------------
template <bool OUT16>
__device__ __forceinline__ void gemm16_body(
    const __half* __restrict__ A, const __half* __restrict__ Bm,
    const float* __restrict__ bias, void* __restrict__ Cv,
    int K, int lda, int ldb, int ldc, int bx, int by)
{
    constexpr int LDH = 72;
    constexpr int STAGE = 128 * LDH;

    extern __shared__ __half smh[];
    __half* As = smh;
    __half* Bs = smh + 2 * STAGE;

    const int tid  = threadIdx.x;
    const int warp = tid >> 5;
    const int lane = tid & 31;
    const int wr = warp & 1, wc = warp >> 1;
    const int g = lane >> 2, t = lane & 3;
    const int row0 = by * 128;
    const int col0 = bx * 128;

    float acc[4][4][4];
#pragma unroll
    for (int i = 0; i < 4; ++i)
#pragma unroll
        for (int j = 0; j < 4; ++j)
#pragma unroll
            for (int q = 0; q < 4; ++q) acc[i][j][q] = 0.0f;

    auto load_tile = [&](int kt) {
        const int st = kt & 1;
        const __half* Ag = A + (size_t)row0 * lda + kt * 64;
        __half* Ad = As + st * STAGE;
#pragma unroll
        for (int i = 0; i < 4; ++i) {
            int id = tid + i * 256;
            int r = id >> 3, c = id & 7;
            cp_async16(smem_u32(Ad + r * LDH + c * 8), Ag + (size_t)r * lda + c * 8);
        }
        const __half* Bg = Bm + (size_t)col0 * ldb + kt * 64;
        __half* Bd = Bs + st * STAGE;
#pragma unroll
        for (int i = 0; i < 4; ++i) {
            int id = tid + i * 256;
            int r = id >> 3, c = id & 7;
            cp_async16(smem_u32(Bd + r * LDH + c * 8), Bg + (size_t)r * ldb + c * 8);
        }
        cp_commit();
    };

    const int T = K >> 6;
    load_tile(0);
    for (int kt = 0; kt < T; ++kt) {
        if (kt + 1 < T) { load_tile(kt + 1); cp_wait_group<1>(); }
        else            { cp_wait_group<0>(); }
        __syncthreads();

        const __half* Ab = As + (kt & 1) * STAGE + (wr * 64) * LDH;
        const __half* Bb = Bs + (kt & 1) * STAGE + (wc * 32) * LDH;
#pragma unroll
        for (int s = 0; s < 4; ++s) {
            const int k0 = s * 16;
            uint32_t a[4][4], b[4][2];
#pragma unroll
            for (int i = 0; i < 4; ++i) {
                const __half* ap = Ab + (i * 16 + g) * LDH + k0 + 2 * t;
                a[i][0] = *(const uint32_t*)(ap);
                a[i][1] = *(const uint32_t*)(ap + 8 * LDH);
                a[i][2] = *(const uint32_t*)(ap + 8);
                a[i][3] = *(const uint32_t*)(ap + 8 * LDH + 8);
            }
#pragma unroll
            for (int j = 0; j < 4; ++j) {
                const __half* bp = Bb + (j * 8 + g) * LDH + k0 + 2 * t;
                b[j][0] = *(const uint32_t*)(bp);
                b[j][1] = *(const uint32_t*)(bp + 8);
            }
#pragma unroll
            for (int i = 0; i < 4; ++i)
#pragma unroll
                for (int j = 0; j < 4; ++j)
                    mma16816(acc[i][j], a[i], b[j]);
        }
        __syncthreads();
    }

#pragma unroll
    for (int i = 0; i < 4; ++i) {
#pragma unroll
        for (int j = 0; j < 4; ++j) {
            const int r = row0 + wr * 64 + i * 16 + g;
            const int c = col0 + wc * 32 + j * 8 + 2 * t;
            const float bx_ = bias[c], by_ = bias[c + 1];
            float v00 = acc[i][j][0] + bx_, v01 = acc[i][j][1] + by_;
            float v10 = acc[i][j][2] + bx_, v11 = acc[i][j][3] + by_;
            if (OUT16) {
                __half* C16 = (__half*)Cv;
                __half2 h0 = __floats2half2_rn(v00, v01);
                __half2 h1 = __floats2half2_rn(v10, v11);
                *(__half2*)(C16 + (size_t)r * ldc + c)       = h0;
                *(__half2*)(C16 + (size_t)(r + 8) * ldc + c) = h1;
            } else {
                float* C32 = (float*)Cv;
                *(float2*)(C32 + (size_t)r * ldc + c)       = make_float2(v00, v01);
                *(float2*)(C32 + (size_t)(r + 8) * ldc + c) = make_float2(v10, v11);
            }
        }
    }
}

struct QKV16 {
    const __half* A[3];
    const __half* W[3];
    const float*  bias[3];
    __half*       C[3];
};
__global__ void __launch_bounds__(256)
gemm16_qkv(QKV16 p)
{
    const int z = blockIdx.z;
    gemm16_body<true>(p.A[z], p.W[z], p.bias[z], p.C[z],
                      HIDDEN_, HIDDEN_, HIDDEN_, HIDDEN_, blockIdx.x, blockIdx.y);
}
__global__ void __launch_bounds__(256)
gemm16_o(const __half* __restrict__ A, const __half* __restrict__ Bm,
         const float* __restrict__ bias, float* __restrict__ C)
{
    gemm16_body<false>(A, Bm, bias, C, HIDDEN_, HIDDEN_, HIDDEN_, HIDDEN_,
                       blockIdx.x, blockIdx.y);
}

// ---------------------------------------------------------------------------
// Per-head V transpose (fp16): VT[bh][d][k] = V[b*SEQ+k][h*HDIM+d]
// ---------------------------------------------------------------------------
__global__ void __launch_bounds__(256)
transpose_v_kernel(const __half* __restrict__ V, __half* __restrict__ VT)
{
    __shared__ __half t[32][34];
    const int bh = blockIdx.z;
    const int b = bh / HEADS_, h = bh % HEADS_;
    const int k0 = blockIdx.x * 32;
    const int d0 = blockIdx.y * 32;
    const int tx = threadIdx.x & 31;
    const int ty = threadIdx.x >> 5;
    const __half* src = V + (size_t)(b * SEQ_) * HIDDEN_ + h * HDIM_;
#pragma unroll
    for (int j = 0; j < 4; ++j)
        t[ty + 8 * j][tx] = src[(size_t)(k0 + ty + 8 * j) * HIDDEN_ + d0 + tx];
    __syncthreads();
    __half* dst = VT + (size_t)bh * HDIM_ * SEQ_;
#pragma unroll
    for (int j = 0; j < 4; ++j)
        dst[(size_t)(d0 + ty + 8 * j) * SEQ_ + k0 + tx] = t[tx][ty + 8 * j];
}

// ---------------------------------------------------------------------------
// Scores + exp (fp16 mma): per CTA = 128x128 S tile, d=64 single stage.
// E = h2exp2(S*temp*log2e) fp16, staged in SMEM (stride 136, conflict-free)
// then coalesced v4 stores. Row partials -> PS. (256,3): measured neutral+.
// ---------------------------------------------------------------------------
__global__ void __launch_bounds__(256, 3)
scores_exp_kernel(const __half* __restrict__ Q, const __half* __restrict__ K,
                  __half* __restrict__ E, float* __restrict__ PS,
                  const float* __restrict__ tptr)
{
    constexpr int LDH = 72;
    constexpr int LDE = 136;
    extern __shared__ __half smh[];
    __half* Qs = smh;                  // 128*72
    __half* Ks = smh + 128 * LDH;      // 128*72
    __half* Es = smh;                  // reuse after mma: 128*136 <= 2*128*72
    __shared__ float red[512];

    const int bx = blockIdx.x;
    const int by = blockIdx.y;
    const int bh = blockIdx.z;
    const int b = bh >> 4, h = bh & 15;
    const int tid = threadIdx.x, lane = tid & 31, warp = tid >> 5;
    const int wr = warp & 1, wc = warp >> 1;
    const int g = lane >> 2, t = lane & 3;
    const float tl2e = (*tptr) * 1.4426950408889634f;

    const __half* Qg = Q + ((size_t)(b * SEQ_) + by * 128) * HIDDEN_ + h * HDIM_;
    const __half* Kg = K + ((size_t)(b * SEQ_) + bx * 128) * HIDDEN_ + h * HDIM_;
    __half* Eg = E + ((size_t)bh * SEQ_ + by * 128) * SEQ_ + bx * 128;

#pragma unroll
    for (int i = 0; i < 4; ++i) {
        int id = tid + i * 256;
        int r = id >> 3, c = id & 7;
        cp_async16(smem_u32(Qs + r * LDH + c * 8), Qg + (size_t)r * HIDDEN_ + c * 8);
    }
#pragma unroll
    for (int i = 0; i < 4; ++i) {
        int id = tid + i * 256;
        int r = id >> 3, c = id & 7;
        cp_async16(smem_u32(Ks + r * LDH + c * 8), Kg + (size_t)r * HIDDEN_ + c * 8);
    }
    cp_commit();
    cp_wait_group<0>();
    __syncthreads();

    float acc[4][4][4];
#pragma unroll
    for (int i = 0; i < 4; ++i)
#pragma unroll
        for (int j = 0; j < 4; ++j)
#pragma unroll
            for (int q = 0; q < 4; ++q) acc[i][j][q] = 0.0f;

#pragma unroll
    for (int s = 0; s < 4; ++s) {
        const int k0 = s * 16;
        uint32_t a[4][4], bf[4][2];
#pragma unroll
        for (int i = 0; i < 4; ++i) {
            const __half* ap = Qs + (wr * 64 + i * 16 + g) * LDH + k0 + 2 * t;
            a[i][0] = *(const uint32_t*)(ap);
            a[i][1] = *(const uint32_t*)(ap + 8 * LDH);
            a[i][2] = *(const uint32_t*)(ap + 8);
            a[i][3] = *(const uint32_t*)(ap + 8 * LDH + 8);
        }
#pragma unroll
        for (int j = 0; j < 4; ++j) {
            const __half* bp = Ks + (wc * 32 + j * 8 + g) * LDH + k0 + 2 * t;
            bf[j][0] = *(const uint32_t*)(bp);
            bf[j][1] = *(const uint32_t*)(bp + 8);
        }
#pragma unroll
        for (int i = 0; i < 4; ++i)
#pragma unroll
            for (int j = 0; j < 4; ++j)
                mma16816(acc[i][j], a[i], bf[j]);
    }
    __syncthreads();                   // Qs/Ks reads complete -> reuse as Es

    // E = 2^(s*temp*log2e) via h2exp2; stage in Es; sums from fp16 values
    float rs0[4], rs1[4];
#pragma unroll
    for (int i = 0; i < 4; ++i) { rs0[i] = 0.f; rs1[i] = 0.f; }
#pragma unroll
    for (int i = 0; i < 4; ++i) {
        const int rA = wr * 64 + i * 16 + g;
#pragma unroll
        for (int j = 0; j < 4; ++j) {
            const int c = wc * 32 + j * 8 + 2 * t;
            __half2 e01 = h2exp2(__floats2half2_rn(acc[i][j][0] * tl2e, acc[i][j][1] * tl2e));
            __half2 e23 = h2exp2(__floats2half2_rn(acc[i][j][2] * tl2e, acc[i][j][3] * tl2e));
            *(__half2*)(Es + rA * LDE + c)       = e01;
            *(__half2*)(Es + (rA + 8) * LDE + c) = e23;
            float2 f0 = __half22float2(e01);
            float2 f1 = __half22float2(e23);
            rs0[i] += f0.x + f0.y;
            rs1[i] += f1.x + f1.y;
        }
    }
    __syncthreads();

    // coalesced v4 stores: 128 rows x 128 halves
#pragma unroll
    for (int p = 0; p < 8; ++p) {
        int id = tid + p * 256;
        int r = id >> 4, cc = id & 15;
        uint4 v = *(const uint4*)(Es + r * LDE + cc * 8);
        st_cs_v4h(Eg + (size_t)r * SEQ_ + cc * 8, v);
    }

    // row-sum reduction
#pragma unroll
    for (int i = 0; i < 4; ++i) {
        rs0[i] += __shfl_xor_sync(0xffffffffu, rs0[i], 1);
        rs0[i] += __shfl_xor_sync(0xffffffffu, rs0[i], 2);
        rs1[i] += __shfl_xor_sync(0xffffffffu, rs1[i], 1);
        rs1[i] += __shfl_xor_sync(0xffffffffu, rs1[i], 2);
    }
    if (t == 0) {
#pragma unroll
        for (int i = 0; i < 4; ++i) {
            red[wc * 128 + wr * 64 + i * 16 + g]     = rs0[i];
            red[wc * 128 + wr * 64 + i * 16 + g + 8] = rs1[i];
        }
    }
    __syncthreads();
    if (tid < 128) {
        float s = red[tid] + red[128 + tid] + red[256 + tid] + red[384 + tid];
        PS[((size_t)bh * SEQ_ + by * 128 + tid) * 16 + bx] = s;
    }
}

// ---------------------------------------------------------------------------
// Context fused (fp16 mma): per CTA = (bh, 128-row strip). K=2048, BK=64.
// Prologue computes invl from PS (inv_reduce folded in; zero redundancy).
// Stream fp16 E -> P fp32 gmem (attn output) + fp16 Ps SMEM; ctx += P@VT^T.
// LDH=72. 8 warps (2 row x 4 col; WN=16). NO min-blocks (R12 spill lesson).
// ---------------------------------------------------------------------------
__global__ void __launch_bounds__(256)
ctx_fused_kernel(const __half* __restrict__ E, const float* __restrict__ PS,
                 const __half* __restrict__ VT, float* __restrict__ P,
                 __half* __restrict__ CTX)
{
    constexpr int LDH = 72;
    constexpr int AS_STAGE = 128 * LDH;    // halves
    constexpr int BS_STAGE = 64 * LDH;
    extern __shared__ __half smh[];
    __half* As = smh;                      // 2 stages
    __half* Bs = smh + 2 * AS_STAGE;       // 2 stages
    __shared__ float s_inv[128];

    const int strip = blockIdx.x;
    const int bh = blockIdx.y;
    const int b = bh >> 4, h = bh & 15;
    const int tid = threadIdx.x, lane = tid & 31, warp = tid >> 5;
    const int wr = warp & 1, wc = warp >> 1;
    const int g = lane >> 2, t = lane & 3;

    const __half* Eg = E + ((size_t)bh * SEQ_ + strip * 128) * SEQ_;
    float*        Pg = P + ((size_t)bh * SEQ_ + strip * 128) * SEQ_;
    const __half* Vg = VT + (size_t)bh * HDIM_ * SEQ_;
    __half*       Cg = CTX + ((size_t)(b * SEQ_) + strip * 128) * HIDDEN_ + h * HDIM_;

    // invl folded in: each of 128 threads sums its row's 16 partials
    if (tid < 128) {
        const float4* ps = (const float4*)(PS + ((size_t)bh * SEQ_ + strip * 128 + tid) * 16);
        float4 a = ps[0], b2 = ps[1], c2 = ps[2], d2 = ps[3];
        float s = (a.x + a.y + a.z + a.w) + (b2.x + b2.y + b2.z + b2.w)
                + (c2.x + c2.y + c2.z + c2.w) + (d2.x + d2.y + d2.z + d2.w);
        s_inv[tid] = 1.0f / s;
    }

    // A tile per kt: 128 rows x 64 halves = 1024 chunks(8h); 4/thread
    uint4 cur[4];
    auto ldgA = [&](int kt, uint4* dst) {
#pragma unroll
        for (int i = 0; i < 4; ++i) {
            int id = tid + i * 256;
            int r = id >> 3, c8 = id & 7;
            dst[i] = ld_cs_v4u(Eg + (size_t)r * SEQ_ + kt * 64 + c8 * 8);
        }
    };
    auto loadB = [&](int kt) {             // 64 d-rows x 64 halves = 512 chunks
        __half* Bd = Bs + (kt & 1) * BS_STAGE;
#pragma unroll
        for (int i = 0; i < 2; ++i) {
            int id = tid + i * 256;
            int r = id >> 3, c8 = id & 7;
            cp_async16(smem_u32(Bd + r * LDH + c8 * 8), Vg + (size_t)r * SEQ_ + kt * 64 + c8 * 8);
        }
        cp_commit();
    };
    auto procA = [&](int kt, uint4* v) {
        __half* Ad = As + (kt & 1) * AS_STAGE;
#pragma unroll
        for (int i = 0; i < 4; ++i) {
            int id = tid + i * 256;
            int r = id >> 3, c8 = id & 7;
            const float inv = s_inv[r];
            float2 f0 = __half22float2(*(__half2*)&v[i].x);
            float2 f1 = __half22float2(*(__half2*)&v[i].y);
            float2 f2 = __half22float2(*(__half2*)&v[i].z);
            float2 f3 = __half22float2(*(__half2*)&v[i].w);
            float p0 = f0.x * inv, p1 = f0.y * inv;
            float p2 = f1.x * inv, p3 = f1.y * inv;
            float p4 = f2.x * inv, p5 = f2.y * inv;
            float p6 = f3.x * inv, p7 = f3.y * inv;
            float* pd = Pg + (size_t)r * SEQ_ + kt * 64 + c8 * 8;
            st_cs_v4f(pd,     make_float4(p0, p1, p2, p3));
            st_cs_v4f(pd + 4, make_float4(p4, p5, p6, p7));
            __half2 q0 = __floats2half2_rn(p0, p1);
            __half2 q1 = __floats2half2_rn(p2, p3);
            __half2 q2 = __floats2half2_rn(p4, p5);
            __half2 q3 = __floats2half2_rn(p6, p7);
            uint4 o;
            o.x = *(uint32_t*)&q0; o.y = *(uint32_t*)&q1;
            o.z = *(uint32_t*)&q2; o.w = *(uint32_t*)&q3;
            *(uint4*)(Ad + r * LDH + c8 * 8) = o;
        }
    };

    float ctx[4][2][4];
#pragma unroll
    for (int i = 0; i < 4; ++i)
#pragma unroll
        for (int j = 0; j < 2; ++j)
#pragma unroll
            for (int q = 0; q < 4; ++q) ctx[i][j][q] = 0.f;

    ldgA(0, cur);
    loadB(0);
    __syncthreads();               // s_inv visible

    for (int kt = 0; kt < 32; ++kt) {
        procA(kt, cur);
        cp_wait_group<0>();        // B tile kt landed
        __syncthreads();           // STS visible; mma kt-1 done everywhere
        if (kt + 1 < 32) {
            ldgA(kt + 1, cur);
            loadB(kt + 1);
        }
        const __half* Ab = As + (kt & 1) * AS_STAGE + (wr * 64) * LDH;
        const __half* Bb = Bs + (kt & 1) * BS_STAGE + (wc * 16) * LDH;
#pragma unroll
        for (int s = 0; s < 4; ++s) {        // 64 keys = 4 x k16
            const int k0 = s * 16;
            uint32_t a[4][4], bf[2][2];
#pragma unroll
            for (int i = 0; i < 4; ++i) {
                const __half* ap = Ab + (i * 16 + g) * LDH + k0 + 2 * t;
                a[i][0] = *(const uint32_t*)(ap);
                a[i][1] = *(const uint32_t*)(ap + 8 * LDH);
                a[i][2] = *(const uint32_t*)(ap + 8);
                a[i][3] = *(const uint32_t*)(ap + 8 * LDH + 8);
            }
#pragma unroll
            for (int j = 0; j < 2; ++j) {
                const __half* bp = Bb + (j * 8 + g) * LDH + k0 + 2 * t;
                bf[j][0] = *(const uint32_t*)(bp);
                bf[j][1] = *(const uint32_t*)(bp + 8);
            }
#pragma unroll
            for (int i = 0; i < 4; ++i)
#pragma unroll
                for (int j = 0; j < 2; ++j)
                    mma16816(ctx[i][j], a[i], bf[j]);
        }
        __syncthreads();
    }

    // write ctx as fp16 (feeds out-projection)
#pragma unroll
    for (int i = 0; i < 4; ++i) {
        const int rA = wr * 64 + i * 16 + g;
#pragma unroll
        for (int j = 0; j < 2; ++j) {
            const int c = wc * 16 + j * 8 + 2 * t;
            __half2 h0 = __floats2half2_rn(ctx[i][j][0], ctx[i][j][1]);
            __half2 h1 = __floats2half2_rn(ctx[i][j][2], ctx[i][j][3]);
            *(__half2*)(Cg + (size_t)rA * HIDDEN_ + c)       = h0;
            *(__half2*)(Cg + (size_t)(rA + 8) * HIDDEN_ + c) = h1;
        }
    }
}

// ---------------------------------------------------------------------------
// Residual + LayerNorm (fp32)
// ---------------------------------------------------------------------------
__global__ void __launch_bounds__(256)
ln_kernel(const float* __restrict__ o, const float* __restrict__ resid,
          const float* __restrict__ gamma, const float* __restrict__ beta,
          float* __restrict__ out)
{
    __shared__ float red1[8], red2[8];
    __shared__ float bmean, binv;

    const size_t row = blockIdx.x;
    const int tid = threadIdx.x;
    const int lane = tid & 31, wid = tid >> 5;
    const float* po = o + row * HIDDEN_;
    const float* pr = resid + row * HIDDEN_;

    float x[4];
    float s = 0.0f, s2 = 0.0f;
#pragma unroll
    for (int u = 0; u < 4; ++u) {
        const int idx = tid + 256 * u;
        x[u] = po[idx] + pr[idx];
        s += x[u];
        s2 += x[u] * x[u];
    }
#pragma unroll
    for (int of = 16; of; of >>= 1) {
        s  += __shfl_xor_sync(0xffffffffu, s,  of);
        s2 += __shfl_xor_sync(0xffffffffu, s2, of);
    }
    if (lane == 0) { red1[wid] = s; red2[wid] = s2; }
    __syncthreads();
    if (wid == 0) {
        float t1 = (lane < 8) ? red1[lane] : 0.0f;
        float t2 = (lane < 8) ? red2[lane] : 0.0f;
#pragma unroll
        for (int of = 16; of; of >>= 1) {
            t1 += __shfl_xor_sync(0xffffffffu, t1, of);
            t2 += __shfl_xor_sync(0xffffffffu, t2, of);
        }
        if (lane == 0) {
            const float mean = t1 * (1.0f / HIDDEN_);
            const float var  = t2 * (1.0f / HIDDEN_) - mean * mean;
            bmean = mean;
            binv  = rsqrtf(var + 1e-5f);
        }
    }
    __syncthreads();
    const float mean = bmean, inv = binv;
#pragma unroll
    for (int u = 0; u < 4; ++u) {
        const int idx = tid + 256 * u;
        out[row * HIDDEN_ + idx] = (x[u] - mean) * inv * gamma[idx] + beta[idx];
    }
}

// ---------------------------------------------------------------------------
static const int DSM_GEMM16   = 4 * 128 * 72 * 2;                  // 73728
static const int DSM_SCORES16 = 2 * 128 * 72 * 2;                  // 36864
static const int DSM_CTX16    = (2 * 128 * 72 + 2 * 64 * 72) * 2;  // 55296

extern "C" void kernel_launch(void* const* d_in, const int* in_sizes, int n_in,
                              void* d_out, int out_size)
{
    const float* query = (const float*)d_in[0];
    const float* key_  = (const float*)d_in[1];
    const float* value = (const float*)d_in[2];
    const float* Wq = (const float*)d_in[3];
    const float* bq = (const float*)d_in[4];
    const float* Wk = (const float*)d_in[5];
    const float* bk = (const float*)d_in[6];
    const float* Wv = (const float*)d_in[7];
    const float* bv = (const float*)d_in[8];
    const float* Wo = (const float*)d_in[9];
    const float* bo = (const float*)d_in[10];
    const float* gamma = (const float*)d_in[11];
    const float* beta  = (const float*)d_in[12];
    const float* temp  = (const float*)d_in[13];

    cudaFuncSetAttribute(gemm16_qkv, cudaFuncAttributeMaxDynamicSharedMemorySize, DSM_GEMM16);
    cudaFuncSetAttribute(gemm16_o,   cudaFuncAttributeMaxDynamicSharedMemorySize, DSM_GEMM16);
    cudaFuncSetAttribute(scores_exp_kernel, cudaFuncAttributeMaxDynamicSharedMemorySize, DSM_SCORES16);
    cudaFuncSetAttribute(ctx_fused_kernel,  cudaFuncAttributeMaxDynamicSharedMemorySize, DSM_CTX16);

    float* out_ln = (float*)d_out;
    __half *pQin, *pKin, *pVin, *pW16, *pQ16, *pK16, *pV16, *pVT16, *pCtx16, *pE;
    float *pO, *pPS, *pP;
    cudaGetSymbolAddress((void**)&pQin,  g_q16in);
    cudaGetSymbolAddress((void**)&pKin,  g_k16in);
    cudaGetSymbolAddress((void**)&pVin,  g_v16in);
    cudaGetSymbolAddress((void**)&pW16,  g_W16);
    cudaGetSymbolAddress((void**)&pQ16,  g_Q16);
    cudaGetSymbolAddress((void**)&pK16,  g_K16);
    cudaGetSymbolAddress((void**)&pV16,  g_V16);
    cudaGetSymbolAddress((void**)&pVT16, g_VT16);
    cudaGetSymbolAddress((void**)&pCtx16,g_ctx16);
    cudaGetSymbolAddress((void**)&pE,    g_E);
    cudaGetSymbolAddress((void**)&pO,    g_o);
    cudaGetSymbolAddress((void**)&pPS,   g_PS);
    if ((long long)out_size >= LN_N + ATT_N) {
        pP = out_ln + LN_N;           // attn_weights are part of the output
    } else {
        cudaGetSymbolAddress((void**)&pP, g_Pfb);
    }
    const int WN = HIDDEN_ * HIDDEN_;

    // --- fp32 -> fp16 conversions (one batched launch)
    {
        Cvt7 c;
        c.src[0] = query; c.dst[0] = pQin;          c.n8[0] = (MTOT_ * HIDDEN_) / 8;
        c.src[1] = key_;  c.dst[1] = pKin;          c.n8[1] = (MTOT_ * HIDDEN_) / 8;
        c.src[2] = value; c.dst[2] = pVin;          c.n8[2] = (MTOT_ * HIDDEN_) / 8;
        c.src[3] = Wq;    c.dst[3] = pW16 + 0ll*WN; c.n8[3] = WN / 8;
        c.src[4] = Wk;    c.dst[4] = pW16 + 1ll*WN; c.n8[4] = WN / 8;
        c.src[5] = Wv;    c.dst[5] = pW16 + 2ll*WN; c.n8[5] = WN / 8;
        c.src[6] = Wo;    c.dst[6] = pW16 + 3ll*WN; c.n8[6] = WN / 8;
        dim3 g((MTOT_ * HIDDEN_ / 8 + 255) / 256, 7, 1);
        cvt_kernel<<<g, 256>>>(c);
    }

    // --- Merged Q/K/V projections (fp16)
    {
        QKV16 p;
        p.A[0] = pQin; p.A[1] = pKin; p.A[2] = pVin;
        p.W[0] = pW16; p.W[1] = pW16 + 1ll*WN; p.W[2] = pW16 + 2ll*WN;
        p.bias[0] = bq; p.bias[1] = bk; p.bias[2] = bv;
        p.C[0] = pQ16; p.C[1] = pK16; p.C[2] = pV16;
        dim3 g(HIDDEN_ / 128, MTOT_ / 128, 3);
        gemm16_qkv<<<g, 256, DSM_GEMM16>>>(p);
    }

    // --- VT transpose (fp16)
    {
        dim3 g(SEQ_ / 32, HDIM_ / 32, BATCH_ * HEADS_);
        transpose_v_kernel<<<g, 256>>>(pV16, pVT16);
    }

    // --- Scores + exp (h2exp2, coalesced fp16 E) + partial sums
    {
        dim3 g(SEQ_ / 128, SEQ_ / 128, BATCH_ * HEADS_);
        scores_exp_kernel<<<g, 256, DSM_SCORES16>>>(pQ16, pK16, pE, pPS, temp);
    }

    // --- Context fused: invl (folded) + P write (fp32) + ctx mma (fp16)
    {
        dim3 g(SEQ_ / 128, BATCH_ * HEADS_, 1);
        ctx_fused_kernel<<<g, 256, DSM_CTX16>>>(pE, pPS, pVT16, pP, pCtx16);
    }

    // --- Output projection: o = ctx @ Wo^T + bo (fp32 out)
    {
        dim3 g(HIDDEN_ / 128, MTOT_ / 128, 1);
        gemm16_o<<<g, 256, DSM_GEMM16>>>(pCtx16, pW16 + 3ll*WN, bo, pO);
    }

    // --- Residual + LayerNorm
    ln_kernel<<<(unsigned)MTOT_, 256>>>(pO, query, gamma, beta, out_ln);
}